// round 13
// baseline (speedup 1.0000x reference)
#include <cuda_runtime.h>
#include <cuda_bf16.h>
#include <cstdint>
#include <stdint.h>
#include <math.h>

// Problem constants
#define BB 64      // batch
#define TT 256     // time
#define DD 512     // input dim
#define HH 1024    // hidden
#define G3 3072    // 3*H
#define G2 2048    // 2*H
#define NB 128     // persistent CTAs
#define NTH 256    // threads per CTA

// smem strides (floats)
#define SWS  132   // weight chunk row stride (128 cols)
#define ASTR 36    // A slab row stride (32 cols)

// ---------------- scratch (device globals; no allocs allowed) ----------------
__device__ float g_ig[(size_t)TT * BB * G3];     // [T][B][3H] precomputed input gates
__device__ float g_p[BB * G3];                   // [B][3H] peephole gates
__device__ float g_hb[2][BB * HH];               // hidden state, parity buffered (tf32-rounded)
__device__ float g_rhb[2][BB * HH];              // resetgate*h, parity buffered (tf32-rounded)
__device__ float g_p1r[2][16][8][4096];          // [par][tile][ks][b][wrow] partials h@Wh_r^T
__device__ float g_p1i[2][16][8][4096];          // [par][tile][ks][b][wrow] partials h@Wh_i^T
__device__ float g_part2[2][16][8][4096];        // [par][tile][ks][b][wrow] partials rh@Wc^T
__device__ float g_Wi_t[G3 * DD];                // tf32-rounded Wi
__device__ float g_Wp_t[G3 * HH];                // tf32-rounded Wp

// dependency flags (monotonic counters, one 128B line each)
__device__ unsigned g_flagD[8 * 32];    // per 128-col h group, 16 producers/step
__device__ unsigned g_flagAr[16 * 32];  // per tile, 8 producers/step
__device__ unsigned g_flagAi[16 * 32];  // per tile, 8 producers/step
__device__ unsigned g_flagB[8 * 32];    // per 128-col rh group, 16 producers/step
__device__ unsigned g_flagC[16 * 32];   // per tile, 8 producers/step

// ---------------- tf32 / mma helpers ----------------
__device__ __forceinline__ unsigned f2tf32(float f) {
    unsigned u;
    asm("cvt.rna.tf32.f32 %0, %1;" : "=r"(u) : "f"(f));
    return u;
}
__device__ __forceinline__ float rndf(float f) { return __uint_as_float(f2tf32(f)); }

__device__ __forceinline__ void mma_tf32(float c[4],
                                         unsigned a0, unsigned a1, unsigned a2, unsigned a3,
                                         unsigned b0, unsigned b1)
{
    asm volatile("mma.sync.aligned.m16n8k8.row.col.f32.tf32.tf32.f32 "
                 "{%0,%1,%2,%3},{%4,%5,%6,%7},{%8,%9},{%0,%1,%2,%3};"
                 : "+f"(c[0]), "+f"(c[1]), "+f"(c[2]), "+f"(c[3])
                 : "r"(a0), "r"(a1), "r"(a2), "r"(a3), "r"(b0), "r"(b1));
}

__device__ __forceinline__ void cp16(float* sdst, const float* gsrc) {
    unsigned sa = (unsigned)__cvta_generic_to_shared(sdst);
    asm volatile("cp.async.cg.shared.global [%0], [%1], 16;\n" :: "r"(sa), "l"(gsrc));
}
#define CPA_COMMIT asm volatile("cp.async.commit_group;\n")
#define CPA_WAIT1  asm volatile("cp.async.wait_group 1;\n")
#define CPA_WAIT0  asm volatile("cp.async.wait_group 0;\n")
#define PF_L2(a)   asm volatile("prefetch.global.L2 [%0];" :: "l"(a))

// ---- flag primitives ----
__device__ __forceinline__ void wait_flag(const unsigned* p, unsigned target) {
    unsigned v;
    do {
        asm volatile("ld.acquire.gpu.b32 %0, [%1];" : "=r"(v) : "l"(p) : "memory");
    } while (v < target);
}
__device__ __forceinline__ void signal_flag(unsigned* p, int tid) {
    __syncthreads();
    if (tid == 0)
        asm volatile("red.add.release.gpu.u32 [%0], 1;" :: "l"(p) : "memory");
}

__device__ __forceinline__ float sigmoidf_(float x) { return 1.0f / (1.0f + expf(-x)); }

// ---------------- weight rounding prologue (Wi, Wp) ----------------
__global__ void round_tf32_kernel(const float* __restrict__ src, float* __restrict__ dst, int n)
{
    int i = blockIdx.x * 256 + threadIdx.x;
    if (i < n) dst[i] = rndf(src[i]);
}

// ---------------- software grid barrier (init only) ----------------
__device__ unsigned g_barcnt = 0;
__device__ volatile unsigned g_bargen = 0;

__device__ __forceinline__ void grid_sync() {
    __syncthreads();
    if (threadIdx.x == 0) {
        __threadfence();
        unsigned g0 = g_bargen;
        unsigned arrived = atomicAdd(&g_barcnt, 1);
        if (arrived == NB - 1) {
            g_barcnt = 0;
            __threadfence();
            g_bargen = g0 + 1;
        } else {
            while (g_bargen == g0) { }
        }
        __threadfence();
    }
    __syncthreads();
}

// ---------------- standalone mma GEMM with bias (ig, p) ----------------
__global__ void __launch_bounds__(NTH)
mma_gemm_bias(const float* __restrict__ A, const float* __restrict__ Wt,
              const float* __restrict__ bias, float* __restrict__ C,
              int K, int N, int xmap)
{
    __shared__ float As[64][36];
    __shared__ float Ws[64][36];
    int tid = threadIdx.x;
    int wid = tid >> 5, lane = tid & 31;
    int wr = wid & 3, wc = wid >> 2;
    int grp = lane >> 2, qd = lane & 3;
    int m0 = blockIdx.y * 64;
    int n0 = blockIdx.x * 64;

    size_t arow[2];
    {
        int r = tid >> 3;
        #pragma unroll
        for (int hh = 0; hh < 2; hh++) {
            int m = m0 + r + 32 * hh;
            if (xmap) { int t = m >> 6, b = m & 63; arow[hh] = ((size_t)b * TT + t) * (size_t)K; }
            else      { arow[hh] = (size_t)m * K; }
        }
    }

    float acc[4][4] = {};
    int c = (tid & 7) * 4;

    for (int k0 = 0; k0 < K; k0 += 32) {
        #pragma unroll
        for (int hh = 0; hh < 2; hh++) {
            float4 v = *reinterpret_cast<const float4*>(A + arow[hh] + k0 + c);
            v.x = rndf(v.x); v.y = rndf(v.y); v.z = rndf(v.z); v.w = rndf(v.w);
            *reinterpret_cast<float4*>(&As[(tid >> 3) + 32 * hh][c]) = v;
        }
        {
            int r = tid >> 3;
            #pragma unroll
            for (int hh = 0; hh < 2; hh++) {
                float4 v = *reinterpret_cast<const float4*>(Wt + (size_t)(n0 + r + 32*hh) * K + k0 + c);
                *reinterpret_cast<float4*>(&Ws[r + 32*hh][c]) = v;
            }
        }
        __syncthreads();
        #pragma unroll
        for (int k8 = 0; k8 < 4; k8++) {
            int kb = k8 * 8;
            unsigned a0 = __float_as_uint(As[16*wr + grp    ][kb + qd    ]);
            unsigned a1 = __float_as_uint(As[16*wr + grp + 8][kb + qd    ]);
            unsigned a2 = __float_as_uint(As[16*wr + grp    ][kb + qd + 4]);
            unsigned a3 = __float_as_uint(As[16*wr + grp + 8][kb + qd + 4]);
            #pragma unroll
            for (int j = 0; j < 4; j++) {
                int nl = 32*wc + 8*j + grp;
                unsigned b0 = __float_as_uint(Ws[nl][kb + qd    ]);
                unsigned b1 = __float_as_uint(Ws[nl][kb + qd + 4]);
                mma_tf32(acc[j], a0, a1, a2, a3, b0, b1);
            }
        }
        __syncthreads();
    }

    #pragma unroll
    for (int half = 0; half < 2; half++) {
        int m = m0 + 16*wr + grp + 8*half;
        #pragma unroll
        for (int j = 0; j < 4; j++) {
            int n = n0 + 32*wc + 8*j + 2*qd;
            float2 v;
            v.x = acc[j][2*half + 0] + bias[n];
            v.y = acc[j][2*half + 1] + bias[n + 1];
            *reinterpret_cast<float2*>(&C[(size_t)m * N + n]) = v;
        }
    }
}

// ---------------- in-scan 64x64 GEMM over K=128 (4 slabs, cp.async 2-deep) ----
__device__ __forceinline__ void gemm_tile64(const float* __restrict__ srcA,
                                            const float* __restrict__ sW,
                                            float* __restrict__ sA,
                                            float* __restrict__ dst,
                                            int wr, int wcx, int grp, int qd,
                                            int rowA, int ldr, int ldc)
{
    float acc[4][4] = {};
    #pragma unroll
    for (int s = 0; s < 2; s++) {
        float* d = sA + s * 64 * ASTR;
        const float* src = srcA + s * 32;
        cp16(d + ldr * ASTR + ldc,       src + (size_t)ldr * HH + ldc);
        cp16(d + (ldr+32) * ASTR + ldc,  src + (size_t)(ldr+32) * HH + ldc);
        CPA_COMMIT;
    }
    #pragma unroll
    for (int s = 0; s < 4; s++) {
        if (s < 3) { CPA_WAIT1; } else { CPA_WAIT0; }
        __syncthreads();
        const float* hbp = sA + (s & 1) * 64 * ASTR;
        const float* wb = sW + s * 32;
        #pragma unroll
        for (int k8 = 0; k8 < 4; k8++) {
            int kb = k8 * 8;
            unsigned a0 = __float_as_uint(hbp[(rowA    ) * ASTR + kb + qd    ]);
            unsigned a1 = __float_as_uint(hbp[(rowA + 8) * ASTR + kb + qd    ]);
            unsigned a2 = __float_as_uint(hbp[(rowA    ) * ASTR + kb + qd + 4]);
            unsigned a3 = __float_as_uint(hbp[(rowA + 8) * ASTR + kb + qd + 4]);
            #pragma unroll
            for (int j = 0; j < 4; j++) {
                int nl = 32*wcx + 8*j + grp;
                unsigned b0 = __float_as_uint(wb[nl * SWS + kb + qd    ]);
                unsigned b1 = __float_as_uint(wb[nl * SWS + kb + qd + 4]);
                mma_tf32(acc[j], a0, a1, a2, a3, b0, b1);
            }
        }
        __syncthreads();
        if (s + 2 < 4) {
            float* d = sA + (s & 1) * 64 * ASTR;
            const float* src = srcA + (s + 2) * 32;
            cp16(d + ldr * ASTR + ldc,       src + (size_t)ldr * HH + ldc);
            cp16(d + (ldr+32) * ASTR + ldc,  src + (size_t)(ldr+32) * HH + ldc);
            CPA_COMMIT;
        }
    }
    #pragma unroll
    for (int half = 0; half < 2; half++) {
        int m = 16*wr + grp + 8*half;
        #pragma unroll
        for (int j = 0; j < 4; j++) {
            int n = 32*wcx + 8*j + 2*qd;
            float2 v;
            v.x = acc[j][2*half + 0];
            v.y = acc[j][2*half + 1];
            __stcg(reinterpret_cast<float2*>(dst + m * 64 + n), v);
        }
    }
}

// ---------------- persistent scan kernel (5-phase flag dataflow) ----------------
__global__ void __launch_bounds__(NTH, 1)
scan_kernel(const float* __restrict__ h0,
            const float* __restrict__ Wh, const float* __restrict__ bh,
            const float* __restrict__ Wc, const float* __restrict__ bc,
            float* __restrict__ out, int want_hT)
{
    extern __shared__ float sm[];
    float* sWR = sm;                      // [64][SWS] Wh_r chunk
    float* sWI = sWR + 64 * SWS;          // [64][SWS] Wh_i chunk
    float* sWC = sWI + 64 * SWS;          // [64][SWS] Wc chunk
    float* sA  = sWC + 64 * SWS;          // [2][64][ASTR] A slabs
    float* sH  = sA + 2 * 64 * ASTR;      // [64][8] own-column h

    const int job  = blockIdx.x;
    const int tid  = threadIdx.x;
    const int wid  = tid >> 5, lane = tid & 31;
    const int wr   = wid & 3, wcx = wid >> 2;
    const int grp  = lane >> 2, qd = lane & 3;
    const int rowA = 16 * wr + grp;

    const int TL = job >> 3;        // tile 0..15 (64 j-cols / w-rows)
    const int KS = job & 7;         // K chunk 0..7 (128 cols)
    const int k0 = 128 * KS;
    const int jc0 = 8 * job;        // owned cols [jc0, jc0+8) = 64*TL + 8*KS
    const int jloc = 8 * KS;        // local col offset within tile TL

    const int ldr = tid >> 3;
    const int ldc = (tid & 7) * 4;

    // ---- reset flags ----
    if (tid == 0) {
        if (job < 16) { g_flagAr[job * 32] = 0; g_flagAi[job * 32] = 0; g_flagC[job * 32] = 0; }
        if (job < 8)  { g_flagD[job * 32] = 0; g_flagB[job * 32] = 0; }
    }

    // ---- prologue: persistent weight chunks into smem (tf32-rounded) ----
    #pragma unroll
    for (int i = 0; i < 8; i++) {
        int fi  = tid + i * NTH;       // 0..2047 float4s
        int row = fi >> 5;             // 0..63
        int c4  = (fi & 31) * 4;       // 0..124
        {
            float4 v = *reinterpret_cast<const float4*>(Wh + (size_t)(64 * TL + row) * HH + k0 + c4);
            v.x = rndf(v.x); v.y = rndf(v.y); v.z = rndf(v.z); v.w = rndf(v.w);
            *reinterpret_cast<float4*>(sWR + row * SWS + c4) = v;
        }
        {
            float4 v = *reinterpret_cast<const float4*>(Wh + (size_t)(HH + 64 * TL + row) * HH + k0 + c4);
            v.x = rndf(v.x); v.y = rndf(v.y); v.z = rndf(v.z); v.w = rndf(v.w);
            *reinterpret_cast<float4*>(sWI + row * SWS + c4) = v;
        }
        {
            float4 v = *reinterpret_cast<const float4*>(Wc + (size_t)(64 * TL + row) * HH + k0 + c4);
            v.x = rndf(v.x); v.y = rndf(v.y); v.z = rndf(v.z); v.w = rndf(v.w);
            *reinterpret_cast<float4*>(sWC + row * SWS + c4) = v;
        }
    }
    // init hbuf[0] = round(h0) and own-column smem h
    {
        int gtid = job * NTH + tid;
        float v0 = rndf(h0[gtid]);
        float v1 = rndf(h0[gtid + NB * NTH]);
        __stcg(&g_hb[0][gtid], v0);
        __stcg(&g_hb[0][gtid + NB * NTH], v1);
        #pragma unroll
        for (int it = 0; it < 2; it++) {
            int e = tid + it * NTH;
            int b = e >> 3, jl = e & 7;
            sH[e] = rndf(h0[b * HH + jc0 + jl]);
        }
    }
    grid_sync();   // once: flags reset + h init visible everywhere

    for (int t = 0; t < TT; t++) {
        const int par = t & 1;
        const float* igt = g_ig + (size_t)t * BB * G3;
        const float* hb_g = g_hb[par];

        // prefetch this step's ig slices into L2
        #pragma unroll
        for (int it = 0; it < 2; it++) {
            int e = tid + it * NTH;
            int b = e >> 3, jl = e & 7;
            const float* base = igt + (size_t)b * G3 + jc0 + jl;
            PF_L2(base);
            PF_L2(base + HH);
            PF_L2(base + G2);
        }

        // ===== Phase A_r: p1r[TL][KS] = h @ Wh_r^T; needs flagD[KS] >= 16t =====
        wait_flag(&g_flagD[KS * 32], 16u * t);
        __syncthreads();
        gemm_tile64(hb_g + k0, sWR, sA, &g_p1r[par][TL][KS][0],
                    wr, wcx, grp, qd, rowA, ldr, ldc);
        signal_flag(&g_flagAr[TL * 32], tid);

        // ===== Phase B: r-gate for own 8 cols; needs flagAr[TL] >= 8(t+1) =====
        wait_flag(&g_flagAr[TL * 32], 8u * (t + 1));
        {
            const float* p1 = &g_p1r[par][TL][0][0];
            #pragma unroll
            for (int it = 0; it < 2; it++) {
                int e = tid + it * NTH;
                int b = e >> 3, jl = e & 7;
                int jj = jloc + jl;
                int j  = jc0 + jl;
                float hr = bh[j];
                #pragma unroll
                for (int ks = 0; ks < 8; ks++)
                    hr += __ldcg(p1 + ks * 4096 + b * 64 + jj);
                size_t bg = (size_t)b * G3;
                float r = sigmoidf_(igt[bg + j] + g_p[bg + j] + hr);
                __stcg(&g_rhb[par][b * HH + j], rndf(r * sH[e]));
            }
        }
        signal_flag(&g_flagB[(job >> 4) * 32], tid);

        // ===== Phase A_i (off critical path): p1i[TL][KS] = h @ Wh_i^T =====
        __syncthreads();
        gemm_tile64(hb_g + k0, sWI, sA, &g_p1i[par][TL][KS][0],
                    wr, wcx, grp, qd, rowA, ldr, ldc);
        signal_flag(&g_flagAi[TL * 32], tid);

        // ===== Phase C: part2[TL][KS] = rh @ Wc^T; needs flagB[KS] >= 16(t+1) =====
        wait_flag(&g_flagB[KS * 32], 16u * (t + 1));
        __syncthreads();
        gemm_tile64(g_rhb[par] + k0, sWC, sA, &g_part2[par][TL][KS][0],
                    wr, wcx, grp, qd, rowA, ldr, ldc);
        signal_flag(&g_flagC[TL * 32], tid);

        // ===== Phase D: i-gate + newgate + blend; needs flagC[TL], flagAi[TL] >= 8(t+1) =====
        wait_flag(&g_flagC[TL * 32], 8u * (t + 1));
        wait_flag(&g_flagAi[TL * 32], 8u * (t + 1));
        {
            const float* p2  = &g_part2[par][TL][0][0];
            const float* p1i = &g_p1i[par][TL][0][0];
            float* hb_n = g_hb[par ^ 1];
            #pragma unroll
            for (int it = 0; it < 2; it++) {
                int e = tid + it * NTH;
                int b = e >> 3, jl = e & 7;
                int jj = jloc + jl;
                int j  = jc0 + jl;
                float hn = bc[j];
                float hi = bh[HH + j];
                #pragma unroll
                for (int ks = 0; ks < 8; ks++) {
                    hn += __ldcg(p2  + ks * 4096 + b * 64 + jj);
                    hi += __ldcg(p1i + ks * 4096 + b * 64 + jj);
                }
                size_t bg = (size_t)b * G3;
                float gi = sigmoidf_(igt[bg + HH + j] + g_p[bg + HH + j] + hi);
                float n  = tanhf(igt[bg + G2 + j] + g_p[bg + G2 + j] + hn);
                float hold = sH[e];
                float hy = hold + gi * (n - hold);
                float hr_ = rndf(hy);
                sH[e] = hr_;
                __stcg(&hb_n[b * HH + j], hr_);
                out[((size_t)b * TT + t) * HH + j] = hy;
                if (want_hT && t == TT - 1)
                    out[(size_t)BB * TT * HH + b * HH + j] = hy;
            }
        }
        signal_flag(&g_flagD[(job >> 4) * 32], tid);
    }
}

// ---------------- launch ----------------
extern "C" void kernel_launch(void* const* d_in, const int* in_sizes, int n_in,
                              void* d_out, int out_size)
{
    const float* x   = (const float*)d_in[0];
    const float* h0  = (const float*)d_in[1];
    const float* ctx = (const float*)d_in[2];
    const float* Wi  = (const float*)d_in[3];
    const float* bi  = (const float*)d_in[4];
    const float* Wh  = (const float*)d_in[5];
    const float* bh  = (const float*)d_in[6];
    const float* Wp  = (const float*)d_in[7];
    const float* bp  = (const float*)d_in[8];
    const float* Wc  = (const float*)d_in[9];
    const float* bc  = (const float*)d_in[10];
    float* out = (float*)d_out;

    float *p_ig, *p_p, *p_Wi, *p_Wp;
    cudaGetSymbolAddress((void**)&p_ig, g_ig);
    cudaGetSymbolAddress((void**)&p_p,  g_p);
    cudaGetSymbolAddress((void**)&p_Wi, g_Wi_t);
    cudaGetSymbolAddress((void**)&p_Wp, g_Wp_t);

    static const int SMEM_SCAN = (3 * 64 * SWS + 2 * 64 * ASTR + 64 * 8) * 4;
    cudaFuncSetAttribute(scan_kernel, cudaFuncAttributeMaxDynamicSharedMemorySize, SMEM_SCAN);

    // prologue: round Wi, Wp to tf32 (Wh, Wc rounded during scan smem load)
    round_tf32_kernel<<<(G3 * DD + 255) / 256, 256>>>(Wi, p_Wi, G3 * DD);
    round_tf32_kernel<<<(G3 * HH + 255) / 256, 256>>>(Wp, p_Wp, G3 * HH);

    // ig_all[t][b][:] = x[b][t][:] @ Wi^T + bi   (time-major)
    mma_gemm_bias<<<dim3(G3 / 64, (TT * BB) / 64), NTH>>>(x, p_Wi, bi, p_ig, DD, G3, 1);

    // p[b][:] = ctx[b] @ Wp^T + bp
    mma_gemm_bias<<<dim3(G3 / 64, 1), NTH>>>(ctx, p_Wp, bp, p_p, HH, G3, 0);

    const int want_hT = (out_size >= (int)((size_t)BB * TT * HH + BB * HH)) ? 1 : 0;

    scan_kernel<<<NB, NTH, SMEM_SCAN>>>(h0, Wh, bh, Wc, bc, out, want_hT);
}

// round 14
// speedup vs baseline: 1.1121x; 1.1121x over previous
#include <cuda_runtime.h>
#include <cuda_bf16.h>
#include <cstdint>
#include <stdint.h>
#include <math.h>

// Problem constants
#define BB 64      // batch
#define TT 256     // time
#define DD 512     // input dim
#define HH 1024    // hidden
#define G3 3072    // 3*H
#define G2 2048    // 2*H
#define KSA 4      // K-split for h@Wh^T  (1024/4 = 256 per chunk)
#define KSC 8      // K-split for rh@Wc^T (1024/8 = 128 per chunk)
#define NB 128     // persistent CTAs
#define NTH 256    // threads per CTA

// smem strides (floats)
#define WASTR 260  // Wh chunk row stride (256 cols)
#define WCSTR 132  // Wc chunk row stride (128 cols)
#define ASTR  36   // A slab row stride (32 cols)

// ---------------- scratch (device globals; no allocs allowed) ----------------
__device__ float g_ig[(size_t)TT * BB * G3];     // [T][B][3H] precomputed input gates
__device__ float g_p[BB * G3];                   // [B][3H] peephole gates
__device__ float g_hb[2][BB * HH];               // hidden state, parity buffered (tf32-rounded)
__device__ float g_rhb[2][BB * HH];              // resetgate*h, parity buffered (tf32-rounded)
__device__ float g_part1[2][32 * KSA * 64 * 64]; // [par][tileA][ks][m][n] partials h@Wh^T
__device__ float g_part2[2][16 * KSC * 64 * 64]; // [par][tileC][ks][m][n] partials rh@Wc^T
__device__ float g_Wi_t[G3 * DD];                // tf32-rounded Wi
__device__ float g_Wp_t[G3 * HH];                // tf32-rounded Wp

// dependency flags (monotonic counters, one 128B line each)
__device__ unsigned g_flagA[32 * 32];   // per tileA, 4 producers/step
__device__ unsigned g_flagB[8 * 32];    // per 128-col group, 16 producers/step
__device__ unsigned g_flagC[16 * 32];   // per tileC, 8 producers/step
__device__ unsigned g_flagD[4 * 32];    // per 256-col group, 32 producers/step

// ---------------- tf32 / mma helpers ----------------
__device__ __forceinline__ unsigned f2tf32(float f) {
    unsigned u;
    asm("cvt.rna.tf32.f32 %0, %1;" : "=r"(u) : "f"(f));
    return u;
}
__device__ __forceinline__ float rndf(float f) { return __uint_as_float(f2tf32(f)); }

__device__ __forceinline__ void mma_tf32(float c[4],
                                         unsigned a0, unsigned a1, unsigned a2, unsigned a3,
                                         unsigned b0, unsigned b1)
{
    asm volatile("mma.sync.aligned.m16n8k8.row.col.f32.tf32.tf32.f32 "
                 "{%0,%1,%2,%3},{%4,%5,%6,%7},{%8,%9},{%0,%1,%2,%3};"
                 : "+f"(c[0]), "+f"(c[1]), "+f"(c[2]), "+f"(c[3])
                 : "r"(a0), "r"(a1), "r"(a2), "r"(a3), "r"(b0), "r"(b1));
}

__device__ __forceinline__ void cp16(float* sdst, const float* gsrc) {
    unsigned sa = (unsigned)__cvta_generic_to_shared(sdst);
    asm volatile("cp.async.cg.shared.global [%0], [%1], 16;\n" :: "r"(sa), "l"(gsrc));
}
#define CPA_COMMIT asm volatile("cp.async.commit_group;\n")
#define CPA_WAIT1  asm volatile("cp.async.wait_group 1;\n")
#define CPA_WAIT0  asm volatile("cp.async.wait_group 0;\n")
#define PF_L2(a)   asm volatile("prefetch.global.L2 [%0];" :: "l"(a))

// ---- flag primitives ----
__device__ __forceinline__ void wait_flag(const unsigned* p, unsigned target) {
    unsigned v;
    do {
        asm volatile("ld.acquire.gpu.b32 %0, [%1];" : "=r"(v) : "l"(p) : "memory");
    } while (v < target);
}
__device__ __forceinline__ void signal_flag(unsigned* p, int tid) {
    __syncthreads();
    if (tid == 0)
        asm volatile("red.add.release.gpu.u32 [%0], 1;" :: "l"(p) : "memory");
}

__device__ __forceinline__ float sigmoidf_(float x) { return 1.0f / (1.0f + expf(-x)); }

// ---------------- weight rounding prologue (Wi, Wp) ----------------
__global__ void round_tf32_kernel(const float* __restrict__ src, float* __restrict__ dst, int n)
{
    int i = blockIdx.x * 256 + threadIdx.x;
    if (i < n) dst[i] = rndf(src[i]);
}

// ---------------- software grid barrier (init only) ----------------
__device__ unsigned g_barcnt = 0;
__device__ volatile unsigned g_bargen = 0;

__device__ __forceinline__ void grid_sync() {
    __syncthreads();
    if (threadIdx.x == 0) {
        __threadfence();
        unsigned g0 = g_bargen;
        unsigned arrived = atomicAdd(&g_barcnt, 1);
        if (arrived == NB - 1) {
            g_barcnt = 0;
            __threadfence();
            g_bargen = g0 + 1;
        } else {
            while (g_bargen == g0) { }
        }
        __threadfence();
    }
    __syncthreads();
}

// ---------------- standalone mma GEMM with bias (ig, p) ----------------
__global__ void __launch_bounds__(NTH)
mma_gemm_bias(const float* __restrict__ A, const float* __restrict__ Wt,
              const float* __restrict__ bias, float* __restrict__ C,
              int K, int N, int xmap)
{
    __shared__ float As[64][36];
    __shared__ float Ws[64][36];
    int tid = threadIdx.x;
    int wid = tid >> 5, lane = tid & 31;
    int wr = wid & 3, wc = wid >> 2;
    int grp = lane >> 2, qd = lane & 3;
    int m0 = blockIdx.y * 64;
    int n0 = blockIdx.x * 64;

    size_t arow[2];
    {
        int r = tid >> 3;
        #pragma unroll
        for (int hh = 0; hh < 2; hh++) {
            int m = m0 + r + 32 * hh;
            if (xmap) { int t = m >> 6, b = m & 63; arow[hh] = ((size_t)b * TT + t) * (size_t)K; }
            else      { arow[hh] = (size_t)m * K; }
        }
    }

    float acc[4][4] = {};
    int c = (tid & 7) * 4;

    for (int k0 = 0; k0 < K; k0 += 32) {
        #pragma unroll
        for (int hh = 0; hh < 2; hh++) {
            float4 v = *reinterpret_cast<const float4*>(A + arow[hh] + k0 + c);
            v.x = rndf(v.x); v.y = rndf(v.y); v.z = rndf(v.z); v.w = rndf(v.w);
            *reinterpret_cast<float4*>(&As[(tid >> 3) + 32 * hh][c]) = v;
        }
        {
            int r = tid >> 3;
            #pragma unroll
            for (int hh = 0; hh < 2; hh++) {
                float4 v = *reinterpret_cast<const float4*>(Wt + (size_t)(n0 + r + 32*hh) * K + k0 + c);
                *reinterpret_cast<float4*>(&Ws[r + 32*hh][c]) = v;
            }
        }
        __syncthreads();
        #pragma unroll
        for (int k8 = 0; k8 < 4; k8++) {
            int kb = k8 * 8;
            unsigned a0 = __float_as_uint(As[16*wr + grp    ][kb + qd    ]);
            unsigned a1 = __float_as_uint(As[16*wr + grp + 8][kb + qd    ]);
            unsigned a2 = __float_as_uint(As[16*wr + grp    ][kb + qd + 4]);
            unsigned a3 = __float_as_uint(As[16*wr + grp + 8][kb + qd + 4]);
            #pragma unroll
            for (int j = 0; j < 4; j++) {
                int nl = 32*wc + 8*j + grp;
                unsigned b0 = __float_as_uint(Ws[nl][kb + qd    ]);
                unsigned b1 = __float_as_uint(Ws[nl][kb + qd + 4]);
                mma_tf32(acc[j], a0, a1, a2, a3, b0, b1);
            }
        }
        __syncthreads();
    }

    #pragma unroll
    for (int half = 0; half < 2; half++) {
        int m = m0 + 16*wr + grp + 8*half;
        #pragma unroll
        for (int j = 0; j < 4; j++) {
            int n = n0 + 32*wc + 8*j + 2*qd;
            float2 v;
            v.x = acc[j][2*half + 0] + bias[n];
            v.y = acc[j][2*half + 1] + bias[n + 1];
            *reinterpret_cast<float2*>(&C[(size_t)m * N + n]) = v;
        }
    }
}

// ---------------- persistent scan kernel (flag-based dataflow) ----------------
__global__ void __launch_bounds__(NTH, 1)
scan_kernel(const float* __restrict__ h0,
            const float* __restrict__ Wh, const float* __restrict__ bh,
            const float* __restrict__ Wc, const float* __restrict__ bc,
            float* __restrict__ out, int want_hT)
{
    extern __shared__ float sm[];
    float* sWA = sm;                            // [64][WASTR] interleaved Wh tile
    float* sWC = sWA + 64 * WASTR;              // [64][WCSTR] Wc chunk
    float* sA  = sWC + 64 * WCSTR;              // [2][64][ASTR] A slabs
    float* sH  = sA + 2 * 64 * ASTR;            // [64][8] own-column h
    float* sGi = sH + 64 * 8;                   // [64][8] own-column inputgate

    const int job  = blockIdx.x;
    const int tid  = threadIdx.x;
    const int wid  = tid >> 5, lane = tid & 31;
    const int wr   = wid & 3, wc = wid >> 2;
    const int grp  = lane >> 2, qd = lane & 3;
    const int rowA = 16 * wr + grp;

    // phase A job: interleaved tileA (32 j-cols, both gates) x ksplit
    const int tileA = job >> 2, ksA = job & 3;
    const int j0A = tileA * 32, k0A = ksA * 256;
    // phase C job
    const int tileC = job >> 3, ksC = job & 7;
    const int n0C = tileC * 64, k0C = ksC * 128;
    // owned columns [jc0, jc0+8) for gate epilogues (B and D)
    const int jc0 = 8 * job;
    const int jjA = jc0 - 32 * tileA;   // local col offset in tileA
    const int nnC = jc0 - 64 * tileC;   // local col offset in tileC

    const int ldr = tid >> 3;
    const int ldc = (tid & 7) * 4;

    // ---- loop-invariant per-thread values (owned column is fixed: 256 % 8 == 0) ----
    const int jown = jc0 + (tid & 7);       // global owned col for both epilogue iters
    const int bown0 = tid >> 3;             // batch row, iter 0
    const int bown1 = 32 + (tid >> 3);      // batch row, iter 1
    const float bhr = bh[jown];
    const float bhi = bh[HH + jown];
    const float bcj = bc[jown];
    const float pr0 = g_p[(size_t)bown0 * G3 + jown];
    const float pr1 = g_p[(size_t)bown1 * G3 + jown];
    const float pi0 = g_p[(size_t)bown0 * G3 + HH + jown];
    const float pi1 = g_p[(size_t)bown1 * G3 + HH + jown];
    const float pn0 = g_p[(size_t)bown0 * G3 + G2 + jown];
    const float pn1 = g_p[(size_t)bown1 * G3 + G2 + jown];

    // ---- reset flags (designated CTAs; prior replay fully finished) ----
    if (tid == 0) {
        if (job < 32) g_flagA[job * 32] = 0;
        if (job < 8)  g_flagB[job * 32] = 0;
        if (job < 16) g_flagC[job * 32] = 0;
        if (job < 4)  g_flagD[job * 32] = 0;
    }

    // ---- prologue: persistent weights into smem (tf32-rounded) ----
    #pragma unroll
    for (int i = 0; i < 16; i++) {
        int fi  = tid + i * NTH;
        int row = fi >> 6;
        int c4  = (fi & 63) * 4;
        int wrow = (row < 32) ? (j0A + row) : (HH + j0A + (row - 32));
        float4 v = *reinterpret_cast<const float4*>(Wh + (size_t)wrow * HH + k0A + c4);
        v.x = rndf(v.x); v.y = rndf(v.y); v.z = rndf(v.z); v.w = rndf(v.w);
        *reinterpret_cast<float4*>(sWA + row * WASTR + c4) = v;
    }
    #pragma unroll
    for (int i = 0; i < 8; i++) {
        int fi  = tid + i * NTH;
        int row = fi >> 5;
        int c4  = (fi & 31) * 4;
        float4 v = *reinterpret_cast<const float4*>(Wc + (size_t)(n0C + row) * HH + k0C + c4);
        v.x = rndf(v.x); v.y = rndf(v.y); v.z = rndf(v.z); v.w = rndf(v.w);
        *reinterpret_cast<float4*>(sWC + row * WCSTR + c4) = v;
    }
    // init hbuf[0] = round(h0) and own-column smem h
    {
        int gtid = job * NTH + tid;
        float v0 = rndf(h0[gtid]);
        float v1 = rndf(h0[gtid + NB * NTH]);
        __stcg(&g_hb[0][gtid], v0);
        __stcg(&g_hb[0][gtid + NB * NTH], v1);
        #pragma unroll
        for (int it = 0; it < 2; it++) {
            int e = tid + it * NTH;
            int b = e >> 3, jl = e & 7;
            sH[e] = rndf(h0[b * HH + jc0 + jl]);
        }
    }
    grid_sync();   // once: flags reset + h init visible everywhere

    for (int t = 0; t < TT; t++) {
        const int par = t & 1;
        const float* igt = g_ig + (size_t)t * BB * G3;
        const float* hb_g = g_hb[par];
        float* part1 = g_part1[par] + (size_t)(tileA * KSA + ksA) * 4096;
        float* part2 = g_part2[par] + (size_t)(tileC * KSC + ksC) * 4096;

        // prefetch this step's ig slices into L2 (covers phases B and D reads)
        {
            const float* base0 = igt + (size_t)bown0 * G3 + jown;
            const float* base1 = igt + (size_t)bown1 * G3 + jown;
            PF_L2(base0); PF_L2(base0 + HH); PF_L2(base0 + G2);
            PF_L2(base1); PF_L2(base1 + HH); PF_L2(base1 + G2);
        }

        // ===== Phase A: part1 = h @ WhT(interleaved tile), needs flagD[ksA] >= 32t =====
        wait_flag(&g_flagD[ksA * 32], 32u * t);
        __syncthreads();
        {
            float acc[4][4] = {};
            #pragma unroll
            for (int s = 0; s < 2; s++) {
                float* dst = sA + s * 64 * ASTR;
                const float* src = hb_g + k0A + s * 32;
                cp16(dst + ldr * ASTR + ldc,       src + (size_t)ldr * HH + ldc);
                cp16(dst + (ldr+32) * ASTR + ldc,  src + (size_t)(ldr+32) * HH + ldc);
                CPA_COMMIT;
            }
            #pragma unroll
            for (int s = 0; s < 8; s++) {
                if (s < 7) { CPA_WAIT1; } else { CPA_WAIT0; }
                __syncthreads();
                const float* hbp = sA + (s & 1) * 64 * ASTR;
                const float* wb = sWA + s * 32;
                #pragma unroll
                for (int k8 = 0; k8 < 4; k8++) {
                    int kb = k8 * 8;
                    unsigned a0 = __float_as_uint(hbp[(rowA    ) * ASTR + kb + qd    ]);
                    unsigned a1 = __float_as_uint(hbp[(rowA + 8) * ASTR + kb + qd    ]);
                    unsigned a2 = __float_as_uint(hbp[(rowA    ) * ASTR + kb + qd + 4]);
                    unsigned a3 = __float_as_uint(hbp[(rowA + 8) * ASTR + kb + qd + 4]);
                    #pragma unroll
                    for (int j = 0; j < 4; j++) {
                        int nl = 32*wc + 8*j + grp;
                        unsigned b0 = __float_as_uint(wb[nl * WASTR + kb + qd    ]);
                        unsigned b1 = __float_as_uint(wb[nl * WASTR + kb + qd + 4]);
                        mma_tf32(acc[j], a0, a1, a2, a3, b0, b1);
                    }
                }
                __syncthreads();
                if (s + 2 < 8) {
                    float* dst = sA + (s & 1) * 64 * ASTR;
                    const float* src = hb_g + k0A + (s + 2) * 32;
                    cp16(dst + ldr * ASTR + ldc,       src + (size_t)ldr * HH + ldc);
                    cp16(dst + (ldr+32) * ASTR + ldc,  src + (size_t)(ldr+32) * HH + ldc);
                    CPA_COMMIT;
                }
            }
            #pragma unroll
            for (int half = 0; half < 2; half++) {
                int m = 16*wr + grp + 8*half;
                #pragma unroll
                for (int j = 0; j < 4; j++) {
                    int n = 32*wc + 8*j + 2*qd;
                    float2 v;
                    v.x = acc[j][2*half + 0];
                    v.y = acc[j][2*half + 1];
                    __stcg(reinterpret_cast<float2*>(part1 + m * 64 + n), v);
                }
            }
        }
        signal_flag(&g_flagA[tileA * 32], tid);

        // ===== Phase B: gates for own 8 columns; needs flagA[tileA] >= 4(t+1) =====
        wait_flag(&g_flagA[tileA * 32], 4u * (t + 1));
        {
            const float* p1 = g_part1[par] + (size_t)tileA * KSA * 4096;
            #pragma unroll
            for (int it = 0; it < 2; it++) {
                int e = tid + it * NTH;
                int b = (it == 0) ? bown0 : bown1;
                int jj = jjA + (tid & 7);
                float hr = bhr, hi = bhi;
                #pragma unroll
                for (int ks = 0; ks < KSA; ks++) {
                    hr += __ldcg(p1 + ks * 4096 + b * 64 + jj);
                    hi += __ldcg(p1 + ks * 4096 + b * 64 + 32 + jj);
                }
                size_t bg = (size_t)b * G3;
                float xr = igt[bg + jown]      + ((it == 0) ? pr0 : pr1);
                float xi = igt[bg + HH + jown] + ((it == 0) ? pi0 : pi1);
                float r  = sigmoidf_(xr + hr);
                float ii = sigmoidf_(xi + hi);
                __stcg(&g_rhb[par][b * HH + jown], rndf(r * sH[e]));
                sGi[e] = ii;
            }
        }
        signal_flag(&g_flagB[(job >> 4) * 32], tid);

        // ===== Phase C: part2 = rh @ WcT; needs flagB[ksC] >= 16(t+1) =====
        wait_flag(&g_flagB[ksC * 32], 16u * (t + 1));
        __syncthreads();
        {
            const float* rh_g = g_rhb[par];
            float acc[4][4] = {};
            #pragma unroll
            for (int s = 0; s < 2; s++) {
                float* dst = sA + s * 64 * ASTR;
                const float* src = rh_g + k0C + s * 32;
                cp16(dst + ldr * ASTR + ldc,       src + (size_t)ldr * HH + ldc);
                cp16(dst + (ldr+32) * ASTR + ldc,  src + (size_t)(ldr+32) * HH + ldc);
                CPA_COMMIT;
            }
            #pragma unroll
            for (int s = 0; s < 4; s++) {
                if (s < 3) { CPA_WAIT1; } else { CPA_WAIT0; }
                __syncthreads();
                const float* hbp = sA + (s & 1) * 64 * ASTR;
                const float* wb = sWC + s * 32;
                #pragma unroll
                for (int k8 = 0; k8 < 4; k8++) {
                    int kb = k8 * 8;
                    unsigned a0 = __float_as_uint(hbp[(rowA    ) * ASTR + kb + qd    ]);
                    unsigned a1 = __float_as_uint(hbp[(rowA + 8) * ASTR + kb + qd    ]);
                    unsigned a2 = __float_as_uint(hbp[(rowA    ) * ASTR + kb + qd + 4]);
                    unsigned a3 = __float_as_uint(hbp[(rowA + 8) * ASTR + kb + qd + 4]);
                    #pragma unroll
                    for (int j = 0; j < 4; j++) {
                        int nl = 32*wc + 8*j + grp;
                        unsigned b0 = __float_as_uint(wb[nl * WCSTR + kb + qd    ]);
                        unsigned b1 = __float_as_uint(wb[nl * WCSTR + kb + qd + 4]);
                        mma_tf32(acc[j], a0, a1, a2, a3, b0, b1);
                    }
                }
                __syncthreads();
                if (s + 2 < 4) {
                    float* dst = sA + (s & 1) * 64 * ASTR;
                    const float* src = rh_g + k0C + (s + 2) * 32;
                    cp16(dst + ldr * ASTR + ldc,       src + (size_t)ldr * HH + ldc);
                    cp16(dst + (ldr+32) * ASTR + ldc,  src + (size_t)(ldr+32) * HH + ldc);
                    CPA_COMMIT;
                }
            }
            #pragma unroll
            for (int half = 0; half < 2; half++) {
                int m = 16*wr + grp + 8*half;
                #pragma unroll
                for (int j = 0; j < 4; j++) {
                    int n = 32*wc + 8*j + 2*qd;
                    float2 v;
                    v.x = acc[j][2*half + 0];
                    v.y = acc[j][2*half + 1];
                    __stcg(reinterpret_cast<float2*>(part2 + m * 64 + n), v);
                }
            }
        }
        signal_flag(&g_flagC[tileC * 32], tid);

        // ===== Phase D: newgate+blend for own 8 columns; needs flagC[tileC] >= 8(t+1) =====
        wait_flag(&g_flagC[tileC * 32], 8u * (t + 1));
        float hyv[2];
        {
            const float* p2 = g_part2[par] + (size_t)tileC * KSC * 4096;
            float* hb_n = g_hb[par ^ 1];
            #pragma unroll
            for (int it = 0; it < 2; it++) {
                int e = tid + it * NTH;
                int b = (it == 0) ? bown0 : bown1;
                int nn = nnC + (tid & 7);
                float hn = bcj;
                #pragma unroll
                for (int ks = 0; ks < KSC; ks++)
                    hn += __ldcg(p2 + ks * 4096 + b * 64 + nn);
                size_t bg = (size_t)b * G3;
                float n = tanhf(igt[bg + G2 + jown] + hn + ((it == 0) ? pn0 : pn1));
                float hold = sH[e];
                float hy = hold + sGi[e] * (n - hold);
                float hr_ = rndf(hy);
                sH[e] = hr_;
                __stcg(&hb_n[b * HH + jown], hr_);
                hyv[it] = hy;
            }
        }
        signal_flag(&g_flagD[(job >> 5) * 32], tid);
        // output stores AFTER the release — off the inter-CTA critical path
        #pragma unroll
        for (int it = 0; it < 2; it++) {
            int b = (it == 0) ? bown0 : bown1;
            out[((size_t)b * TT + t) * HH + jown] = hyv[it];
            if (want_hT && t == TT - 1)
                out[(size_t)BB * TT * HH + b * HH + jown] = hyv[it];
        }
    }
}

// ---------------- launch ----------------
extern "C" void kernel_launch(void* const* d_in, const int* in_sizes, int n_in,
                              void* d_out, int out_size)
{
    const float* x   = (const float*)d_in[0];
    const float* h0  = (const float*)d_in[1];
    const float* ctx = (const float*)d_in[2];
    const float* Wi  = (const float*)d_in[3];
    const float* bi  = (const float*)d_in[4];
    const float* Wh  = (const float*)d_in[5];
    const float* bh  = (const float*)d_in[6];
    const float* Wp  = (const float*)d_in[7];
    const float* bp  = (const float*)d_in[8];
    const float* Wc  = (const float*)d_in[9];
    const float* bc  = (const float*)d_in[10];
    float* out = (float*)d_out;

    float *p_ig, *p_p, *p_Wi, *p_Wp;
    cudaGetSymbolAddress((void**)&p_ig, g_ig);
    cudaGetSymbolAddress((void**)&p_p,  g_p);
    cudaGetSymbolAddress((void**)&p_Wi, g_Wi_t);
    cudaGetSymbolAddress((void**)&p_Wp, g_Wp_t);

    static const int SMEM_SCAN = (64 * WASTR + 64 * WCSTR + 2 * 64 * ASTR + 64 * 8 + 64 * 8) * 4;
    cudaFuncSetAttribute(scan_kernel, cudaFuncAttributeMaxDynamicSharedMemorySize, SMEM_SCAN);

    // prologue: round Wi, Wp to tf32 (Wh, Wc rounded during scan smem load)
    round_tf32_kernel<<<(G3 * DD + 255) / 256, 256>>>(Wi, p_Wi, G3 * DD);
    round_tf32_kernel<<<(G3 * HH + 255) / 256, 256>>>(Wp, p_Wp, G3 * HH);

    // ig_all[t][b][:] = x[b][t][:] @ Wi^T + bi   (time-major)
    mma_gemm_bias<<<dim3(G3 / 64, (TT * BB) / 64), NTH>>>(x, p_Wi, bi, p_ig, DD, G3, 1);

    // p[b][:] = ctx[b] @ Wp^T + bp
    mma_gemm_bias<<<dim3(G3 / 64, 1), NTH>>>(ctx, p_Wp, bp, p_p, HH, G3, 0);

    const int want_hT = (out_size >= (int)((size_t)BB * TT * HH + BB * HH)) ? 1 : 0;

    scan_kernel<<<NB, NTH, SMEM_SCAN>>>(h0, Wh, bh, Wc, bc, out, want_hT);
}

// round 15
// speedup vs baseline: 1.1215x; 1.0085x over previous
#include <cuda_runtime.h>
#include <cuda_bf16.h>
#include <cstdint>
#include <stdint.h>
#include <math.h>

// Problem constants
#define BB 64      // batch
#define TT 256     // time
#define DD 512     // input dim
#define HH 1024    // hidden
#define G3 3072    // 3*H
#define G2 2048    // 2*H
#define KSA 4      // K-split for h@Wh^T  (1024/4 = 256 per chunk)
#define KSC 8      // K-split for rh@Wc^T (1024/8 = 128 per chunk)
#define NB 128     // persistent CTAs
#define NTH 256    // threads per CTA

// smem strides (floats)
#define WASTR 260  // Wh chunk / staged-h row stride (256 cols)
#define WCSTR 132  // Wc chunk / staged-rh row stride (128 cols)

// ---------------- scratch (device globals; no allocs allowed) ----------------
__device__ float g_ig[(size_t)TT * BB * G3];     // [T][B][3H] precomputed input gates
__device__ float g_p[BB * G3];                   // [B][3H] peephole gates
__device__ float g_hb[2][BB * HH];               // hidden state, parity buffered (tf32-rounded)
__device__ float g_rhb[2][BB * HH];              // resetgate*h, parity buffered (tf32-rounded)
__device__ float g_part1[2][32 * KSA * 64 * 64]; // [par][tileA][ks][m][n] partials h@Wh^T
__device__ float g_part2[2][16 * KSC * 64 * 64]; // [par][tileC][ks][m][n] partials rh@Wc^T
__device__ float g_Wi_t[G3 * DD];                // tf32-rounded Wi
__device__ float g_Wp_t[G3 * HH];                // tf32-rounded Wp

// dependency flags (monotonic counters, one 128B line each)
__device__ unsigned g_flagA[32 * 32];   // per tileA, 4 producers/step
__device__ unsigned g_flagB[8 * 32];    // per 128-col group, 16 producers/step
__device__ unsigned g_flagC[16 * 32];   // per tileC, 8 producers/step
__device__ unsigned g_flagD[4 * 32];    // per 256-col group, 32 producers/step

// ---------------- tf32 / mma helpers ----------------
__device__ __forceinline__ unsigned f2tf32(float f) {
    unsigned u;
    asm("cvt.rna.tf32.f32 %0, %1;" : "=r"(u) : "f"(f));
    return u;
}
__device__ __forceinline__ float rndf(float f) { return __uint_as_float(f2tf32(f)); }

__device__ __forceinline__ void mma_tf32(float c[4],
                                         unsigned a0, unsigned a1, unsigned a2, unsigned a3,
                                         unsigned b0, unsigned b1)
{
    asm volatile("mma.sync.aligned.m16n8k8.row.col.f32.tf32.tf32.f32 "
                 "{%0,%1,%2,%3},{%4,%5,%6,%7},{%8,%9},{%0,%1,%2,%3};"
                 : "+f"(c[0]), "+f"(c[1]), "+f"(c[2]), "+f"(c[3])
                 : "r"(a0), "r"(a1), "r"(a2), "r"(a3), "r"(b0), "r"(b1));
}

__device__ __forceinline__ void cp16(float* sdst, const float* gsrc) {
    unsigned sa = (unsigned)__cvta_generic_to_shared(sdst);
    asm volatile("cp.async.cg.shared.global [%0], [%1], 16;\n" :: "r"(sa), "l"(gsrc));
}
#define CPA_COMMIT asm volatile("cp.async.commit_group;\n")
#define CPA_WAIT0  asm volatile("cp.async.wait_group 0;\n")
#define PF_L2(a)   asm volatile("prefetch.global.L2 [%0];" :: "l"(a))

// ---- flag primitives ----
__device__ __forceinline__ void wait_flag(const unsigned* p, unsigned target) {
    unsigned v;
    do {
        asm volatile("ld.acquire.gpu.b32 %0, [%1];" : "=r"(v) : "l"(p) : "memory");
    } while (v < target);
}
__device__ __forceinline__ void signal_flag(unsigned* p, int tid) {
    __syncthreads();
    if (tid == 0)
        asm volatile("red.add.release.gpu.u32 [%0], 1;" :: "l"(p) : "memory");
}

__device__ __forceinline__ float sigmoidf_(float x) { return 1.0f / (1.0f + expf(-x)); }

// ---------------- weight rounding prologue (Wi, Wp) ----------------
__global__ void round_tf32_kernel(const float* __restrict__ src, float* __restrict__ dst, int n)
{
    int i = blockIdx.x * 256 + threadIdx.x;
    if (i < n) dst[i] = rndf(src[i]);
}

// ---------------- software grid barrier (init only) ----------------
__device__ unsigned g_barcnt = 0;
__device__ volatile unsigned g_bargen = 0;

__device__ __forceinline__ void grid_sync() {
    __syncthreads();
    if (threadIdx.x == 0) {
        __threadfence();
        unsigned g0 = g_bargen;
        unsigned arrived = atomicAdd(&g_barcnt, 1);
        if (arrived == NB - 1) {
            g_barcnt = 0;
            __threadfence();
            g_bargen = g0 + 1;
        } else {
            while (g_bargen == g0) { }
        }
        __threadfence();
    }
    __syncthreads();
}

// ---------------- standalone mma GEMM with bias (ig, p) ----------------
__global__ void __launch_bounds__(NTH)
mma_gemm_bias(const float* __restrict__ A, const float* __restrict__ Wt,
              const float* __restrict__ bias, float* __restrict__ C,
              int K, int N, int xmap)
{
    __shared__ float As[64][36];
    __shared__ float Ws[64][36];
    int tid = threadIdx.x;
    int wid = tid >> 5, lane = tid & 31;
    int wr = wid & 3, wc = wid >> 2;
    int grp = lane >> 2, qd = lane & 3;
    int m0 = blockIdx.y * 64;
    int n0 = blockIdx.x * 64;

    size_t arow[2];
    {
        int r = tid >> 3;
        #pragma unroll
        for (int hh = 0; hh < 2; hh++) {
            int m = m0 + r + 32 * hh;
            if (xmap) { int t = m >> 6, b = m & 63; arow[hh] = ((size_t)b * TT + t) * (size_t)K; }
            else      { arow[hh] = (size_t)m * K; }
        }
    }

    float acc[4][4] = {};
    int c = (tid & 7) * 4;

    for (int k0 = 0; k0 < K; k0 += 32) {
        #pragma unroll
        for (int hh = 0; hh < 2; hh++) {
            float4 v = *reinterpret_cast<const float4*>(A + arow[hh] + k0 + c);
            v.x = rndf(v.x); v.y = rndf(v.y); v.z = rndf(v.z); v.w = rndf(v.w);
            *reinterpret_cast<float4*>(&As[(tid >> 3) + 32 * hh][c]) = v;
        }
        {
            int r = tid >> 3;
            #pragma unroll
            for (int hh = 0; hh < 2; hh++) {
                float4 v = *reinterpret_cast<const float4*>(Wt + (size_t)(n0 + r + 32*hh) * K + k0 + c);
                *reinterpret_cast<float4*>(&Ws[r + 32*hh][c]) = v;
            }
        }
        __syncthreads();
        #pragma unroll
        for (int k8 = 0; k8 < 4; k8++) {
            int kb = k8 * 8;
            unsigned a0 = __float_as_uint(As[16*wr + grp    ][kb + qd    ]);
            unsigned a1 = __float_as_uint(As[16*wr + grp + 8][kb + qd    ]);
            unsigned a2 = __float_as_uint(As[16*wr + grp    ][kb + qd + 4]);
            unsigned a3 = __float_as_uint(As[16*wr + grp + 8][kb + qd + 4]);
            #pragma unroll
            for (int j = 0; j < 4; j++) {
                int nl = 32*wc + 8*j + grp;
                unsigned b0 = __float_as_uint(Ws[nl][kb + qd    ]);
                unsigned b1 = __float_as_uint(Ws[nl][kb + qd + 4]);
                mma_tf32(acc[j], a0, a1, a2, a3, b0, b1);
            }
        }
        __syncthreads();
    }

    #pragma unroll
    for (int half = 0; half < 2; half++) {
        int m = m0 + 16*wr + grp + 8*half;
        #pragma unroll
        for (int j = 0; j < 4; j++) {
            int n = n0 + 32*wc + 8*j + 2*qd;
            float2 v;
            v.x = acc[j][2*half + 0] + bias[n];
            v.y = acc[j][2*half + 1] + bias[n + 1];
            *reinterpret_cast<float2*>(&C[(size_t)m * N + n]) = v;
        }
    }
}

// ---------------- persistent scan kernel (flag-based dataflow) ----------------
__global__ void __launch_bounds__(NTH, 1)
scan_kernel(const float* __restrict__ h0,
            const float* __restrict__ Wh, const float* __restrict__ bh,
            const float* __restrict__ Wc, const float* __restrict__ bc,
            float* __restrict__ out, int want_hT)
{
    extern __shared__ float sm[];
    float* sWA = sm;                            // [64][WASTR] interleaved Wh tile
    float* sWC = sWA + 64 * WASTR;              // [64][WCSTR] Wc chunk
    float* sAF = sWC + 64 * WCSTR;              // [64][WASTR] staged A operand (full chunk)
    float* sH  = sAF + 64 * WASTR;              // [64][8] own-column h
    float* sGi = sH + 64 * 8;                   // [64][8] own-column inputgate

    const int job  = blockIdx.x;
    const int tid  = threadIdx.x;
    const int wid  = tid >> 5, lane = tid & 31;
    const int wr   = wid & 3, wc = wid >> 2;
    const int grp  = lane >> 2, qd = lane & 3;
    const int rowA = 16 * wr + grp;

    // phase A job: interleaved tileA (32 j-cols, both gates) x ksplit
    const int tileA = job >> 2, ksA = job & 3;
    const int j0A = tileA * 32, k0A = ksA * 256;
    // phase C job
    const int tileC = job >> 3, ksC = job & 7;
    const int n0C = tileC * 64, k0C = ksC * 128;
    // owned columns [jc0, jc0+8) for gate epilogues (B and D)
    const int jc0 = 8 * job;
    const int jjA = jc0 - 32 * tileA;   // local col offset in tileA
    const int nnC = jc0 - 64 * tileC;   // local col offset in tileC

    // ---- loop-invariant per-thread values (owned column is fixed: 256 % 8 == 0) ----
    const int jown = jc0 + (tid & 7);
    const int bown0 = tid >> 3;
    const int bown1 = 32 + (tid >> 3);
    const float bhr = bh[jown];
    const float bhi = bh[HH + jown];
    const float bcj = bc[jown];
    const float pr0 = g_p[(size_t)bown0 * G3 + jown];
    const float pr1 = g_p[(size_t)bown1 * G3 + jown];
    const float pi0 = g_p[(size_t)bown0 * G3 + HH + jown];
    const float pi1 = g_p[(size_t)bown1 * G3 + HH + jown];
    const float pn0 = g_p[(size_t)bown0 * G3 + G2 + jown];
    const float pn1 = g_p[(size_t)bown1 * G3 + G2 + jown];

    // ---- reset flags ----
    if (tid == 0) {
        if (job < 32) g_flagA[job * 32] = 0;
        if (job < 8)  g_flagB[job * 32] = 0;
        if (job < 16) g_flagC[job * 32] = 0;
        if (job < 4)  g_flagD[job * 32] = 0;
    }

    // ---- prologue: persistent weights into smem (tf32-rounded) ----
    #pragma unroll
    for (int i = 0; i < 16; i++) {
        int fi  = tid + i * NTH;
        int row = fi >> 6;
        int c4  = (fi & 63) * 4;
        int wrow = (row < 32) ? (j0A + row) : (HH + j0A + (row - 32));
        float4 v = *reinterpret_cast<const float4*>(Wh + (size_t)wrow * HH + k0A + c4);
        v.x = rndf(v.x); v.y = rndf(v.y); v.z = rndf(v.z); v.w = rndf(v.w);
        *reinterpret_cast<float4*>(sWA + row * WASTR + c4) = v;
    }
    #pragma unroll
    for (int i = 0; i < 8; i++) {
        int fi  = tid + i * NTH;
        int row = fi >> 5;
        int c4  = (fi & 31) * 4;
        float4 v = *reinterpret_cast<const float4*>(Wc + (size_t)(n0C + row) * HH + k0C + c4);
        v.x = rndf(v.x); v.y = rndf(v.y); v.z = rndf(v.z); v.w = rndf(v.w);
        *reinterpret_cast<float4*>(sWC + row * WCSTR + c4) = v;
    }
    // init hbuf[0] = round(h0) and own-column smem h
    {
        int gtid = job * NTH + tid;
        float v0 = rndf(h0[gtid]);
        float v1 = rndf(h0[gtid + NB * NTH]);
        __stcg(&g_hb[0][gtid], v0);
        __stcg(&g_hb[0][gtid + NB * NTH], v1);
        #pragma unroll
        for (int it = 0; it < 2; it++) {
            int e = tid + it * NTH;
            int b = e >> 3, jl = e & 7;
            sH[e] = rndf(h0[b * HH + jc0 + jl]);
        }
    }
    grid_sync();   // once: flags reset + h init visible everywhere

    for (int t = 0; t < TT; t++) {
        const int par = t & 1;
        const float* igt = g_ig + (size_t)t * BB * G3;
        const float* hb_g = g_hb[par];
        float* part1 = g_part1[par] + (size_t)(tileA * KSA + ksA) * 4096;
        float* part2 = g_part2[par] + (size_t)(tileC * KSC + ksC) * 4096;

        // prefetch this step's ig slices into L2
        {
            const float* base0 = igt + (size_t)bown0 * G3 + jown;
            const float* base1 = igt + (size_t)bown1 * G3 + jown;
            PF_L2(base0); PF_L2(base0 + HH); PF_L2(base0 + G2);
            PF_L2(base1); PF_L2(base1 + HH); PF_L2(base1 + G2);
        }

        // ===== Phase A: part1 = h @ WhT(interleaved tile); single-sync full staging =====
        wait_flag(&g_flagD[ksA * 32], 32u * t);
        __syncthreads();   // protect sAF reuse from previous phase C
        {
            // stage entire 64x256 h chunk
            #pragma unroll
            for (int i = 0; i < 16; i++) {
                int fi  = tid + i * NTH;
                int row = fi >> 6;
                int c4  = (fi & 63) * 4;
                cp16(sAF + row * WASTR + c4, hb_g + k0A + (size_t)row * HH + c4);
            }
            CPA_COMMIT; CPA_WAIT0;
            __syncthreads();

            float acc[4][4] = {};
            #pragma unroll
            for (int s = 0; s < 8; s++) {
                const float* hbp = sAF + s * 32;
                const float* wb  = sWA + s * 32;
                #pragma unroll
                for (int k8 = 0; k8 < 4; k8++) {
                    int kb = k8 * 8;
                    unsigned a0 = __float_as_uint(hbp[(rowA    ) * WASTR + kb + qd    ]);
                    unsigned a1 = __float_as_uint(hbp[(rowA + 8) * WASTR + kb + qd    ]);
                    unsigned a2 = __float_as_uint(hbp[(rowA    ) * WASTR + kb + qd + 4]);
                    unsigned a3 = __float_as_uint(hbp[(rowA + 8) * WASTR + kb + qd + 4]);
                    #pragma unroll
                    for (int j = 0; j < 4; j++) {
                        int nl = 32*wc + 8*j + grp;
                        unsigned b0 = __float_as_uint(wb[nl * WASTR + kb + qd    ]);
                        unsigned b1 = __float_as_uint(wb[nl * WASTR + kb + qd + 4]);
                        mma_tf32(acc[j], a0, a1, a2, a3, b0, b1);
                    }
                }
            }
            #pragma unroll
            for (int half = 0; half < 2; half++) {
                int m = 16*wr + grp + 8*half;
                #pragma unroll
                for (int j = 0; j < 4; j++) {
                    int n = 32*wc + 8*j + 2*qd;
                    float2 v;
                    v.x = acc[j][2*half + 0];
                    v.y = acc[j][2*half + 1];
                    __stcg(reinterpret_cast<float2*>(part1 + m * 64 + n), v);
                }
            }
        }
        signal_flag(&g_flagA[tileA * 32], tid);

        // ===== Phase B: gates for own 8 columns; needs flagA[tileA] >= 4(t+1) =====
        wait_flag(&g_flagA[tileA * 32], 4u * (t + 1));
        {
            const float* p1 = g_part1[par] + (size_t)tileA * KSA * 4096;
            #pragma unroll
            for (int it = 0; it < 2; it++) {
                int e = tid + it * NTH;
                int b = (it == 0) ? bown0 : bown1;
                int jj = jjA + (tid & 7);
                float hr = bhr, hi = bhi;
                #pragma unroll
                for (int ks = 0; ks < KSA; ks++) {
                    hr += __ldcg(p1 + ks * 4096 + b * 64 + jj);
                    hi += __ldcg(p1 + ks * 4096 + b * 64 + 32 + jj);
                }
                size_t bg = (size_t)b * G3;
                float xr = igt[bg + jown]      + ((it == 0) ? pr0 : pr1);
                float xi = igt[bg + HH + jown] + ((it == 0) ? pi0 : pi1);
                float r  = sigmoidf_(xr + hr);
                float ii = sigmoidf_(xi + hi);
                __stcg(&g_rhb[par][b * HH + jown], rndf(r * sH[e]));
                sGi[e] = ii;
            }
        }
        signal_flag(&g_flagB[(job >> 4) * 32], tid);

        // ===== Phase C: part2 = rh @ WcT; single-sync full staging =====
        wait_flag(&g_flagB[ksC * 32], 16u * (t + 1));
        __syncthreads();   // protect sAF reuse from phase A
        {
            const float* rh_g = g_rhb[par];
            // stage entire 64x128 rh chunk
            #pragma unroll
            for (int i = 0; i < 8; i++) {
                int fi  = tid + i * NTH;
                int row = fi >> 5;
                int c4  = (fi & 31) * 4;
                cp16(sAF + row * WCSTR + c4, rh_g + k0C + (size_t)row * HH + c4);
            }
            CPA_COMMIT; CPA_WAIT0;
            __syncthreads();

            float acc[4][4] = {};
            #pragma unroll
            for (int s = 0; s < 4; s++) {
                const float* hbp = sAF + s * 32;
                const float* wb  = sWC + s * 32;
                #pragma unroll
                for (int k8 = 0; k8 < 4; k8++) {
                    int kb = k8 * 8;
                    unsigned a0 = __float_as_uint(hbp[(rowA    ) * WCSTR + kb + qd    ]);
                    unsigned a1 = __float_as_uint(hbp[(rowA + 8) * WCSTR + kb + qd    ]);
                    unsigned a2 = __float_as_uint(hbp[(rowA    ) * WCSTR + kb + qd + 4]);
                    unsigned a3 = __float_as_uint(hbp[(rowA + 8) * WCSTR + kb + qd + 4]);
                    #pragma unroll
                    for (int j = 0; j < 4; j++) {
                        int nl = 32*wc + 8*j + grp;
                        unsigned b0 = __float_as_uint(wb[nl * WCSTR + kb + qd    ]);
                        unsigned b1 = __float_as_uint(wb[nl * WCSTR + kb + qd + 4]);
                        mma_tf32(acc[j], a0, a1, a2, a3, b0, b1);
                    }
                }
            }
            #pragma unroll
            for (int half = 0; half < 2; half++) {
                int m = 16*wr + grp + 8*half;
                #pragma unroll
                for (int j = 0; j < 4; j++) {
                    int n = 32*wc + 8*j + 2*qd;
                    float2 v;
                    v.x = acc[j][2*half + 0];
                    v.y = acc[j][2*half + 1];
                    __stcg(reinterpret_cast<float2*>(part2 + m * 64 + n), v);
                }
            }
        }
        signal_flag(&g_flagC[tileC * 32], tid);

        // ===== Phase D: newgate+blend for own 8 columns; needs flagC[tileC] >= 8(t+1) =====
        wait_flag(&g_flagC[tileC * 32], 8u * (t + 1));
        float hyv[2];
        {
            const float* p2 = g_part2[par] + (size_t)tileC * KSC * 4096;
            float* hb_n = g_hb[par ^ 1];
            #pragma unroll
            for (int it = 0; it < 2; it++) {
                int e = tid + it * NTH;
                int b = (it == 0) ? bown0 : bown1;
                int nn = nnC + (tid & 7);
                float hn = bcj;
                #pragma unroll
                for (int ks = 0; ks < KSC; ks++)
                    hn += __ldcg(p2 + ks * 4096 + b * 64 + nn);
                size_t bg = (size_t)b * G3;
                float n = tanhf(igt[bg + G2 + jown] + hn + ((it == 0) ? pn0 : pn1));
                float hold = sH[e];
                float hy = hold + sGi[e] * (n - hold);
                float hr_ = rndf(hy);
                sH[e] = hr_;
                __stcg(&hb_n[b * HH + jown], hr_);
                hyv[it] = hy;
            }
        }
        signal_flag(&g_flagD[(job >> 5) * 32], tid);
        // output stores AFTER the release — off the inter-CTA critical path
        #pragma unroll
        for (int it = 0; it < 2; it++) {
            int b = (it == 0) ? bown0 : bown1;
            out[((size_t)b * TT + t) * HH + jown] = hyv[it];
            if (want_hT && t == TT - 1)
                out[(size_t)BB * TT * HH + b * HH + jown] = hyv[it];
        }
    }
}

// ---------------- launch ----------------
extern "C" void kernel_launch(void* const* d_in, const int* in_sizes, int n_in,
                              void* d_out, int out_size)
{
    const float* x   = (const float*)d_in[0];
    const float* h0  = (const float*)d_in[1];
    const float* ctx = (const float*)d_in[2];
    const float* Wi  = (const float*)d_in[3];
    const float* bi  = (const float*)d_in[4];
    const float* Wh  = (const float*)d_in[5];
    const float* bh  = (const float*)d_in[6];
    const float* Wp  = (const float*)d_in[7];
    const float* bp  = (const float*)d_in[8];
    const float* Wc  = (const float*)d_in[9];
    const float* bc  = (const float*)d_in[10];
    float* out = (float*)d_out;

    float *p_ig, *p_p, *p_Wi, *p_Wp;
    cudaGetSymbolAddress((void**)&p_ig, g_ig);
    cudaGetSymbolAddress((void**)&p_p,  g_p);
    cudaGetSymbolAddress((void**)&p_Wi, g_Wi_t);
    cudaGetSymbolAddress((void**)&p_Wp, g_Wp_t);

    static const int SMEM_SCAN = (64 * WASTR + 64 * WCSTR + 64 * WASTR + 64 * 8 + 64 * 8) * 4;
    cudaFuncSetAttribute(scan_kernel, cudaFuncAttributeMaxDynamicSharedMemorySize, SMEM_SCAN);

    // prologue: round Wi, Wp to tf32 (Wh, Wc rounded during scan smem load)
    round_tf32_kernel<<<(G3 * DD + 255) / 256, 256>>>(Wi, p_Wi, G3 * DD);
    round_tf32_kernel<<<(G3 * HH + 255) / 256, 256>>>(Wp, p_Wp, G3 * HH);

    // ig_all[t][b][:] = x[b][t][:] @ Wi^T + bi   (time-major)
    mma_gemm_bias<<<dim3(G3 / 64, (TT * BB) / 64), NTH>>>(x, p_Wi, bi, p_ig, DD, G3, 1);

    // p[b][:] = ctx[b] @ Wp^T + bp
    mma_gemm_bias<<<dim3(G3 / 64, 1), NTH>>>(ctx, p_Wp, bp, p_p, HH, G3, 0);

    const int want_hT = (out_size >= (int)((size_t)BB * TT * HH + BB * HH)) ? 1 : 0;

    scan_kernel<<<NB, NTH, SMEM_SCAN>>>(h0, Wh, bh, Wc, bc, out, want_hT);
}